// round 14
// baseline (speedup 1.0000x reference)
#include <cuda_runtime.h>
#include <cuda_bf16.h>

// ---------------------------------------------------------------------------
// QuantumLayerVQC — 3-qubit, 3-layer VQC, B ~ 1M samples.
//
// z(b) = psi(b)^T ReM psi(b), psi = kron_q (cos x_q/2, sin x_q/2),
// ReM = Re(U^dag Z0 U) depends only on q_weights. Per qubit the quadratic
// monomials {c^2, s^2, cs} map to {1, cos x, sin x} (double angle), so z is
// trilinear in m_q = (1, cos x_q, sin x_q) with 27 coefficients D.
//
// SINGLE one-shot kernel, cp.async gather:
//  - every thread issues 8x cp.async.cg 16B (the needed half of each 32B row)
//    into SMEM -> 32KB in flight per block issued by 256 threads in ~64cyc,
//    ~190KB/SM in flight (vs ~5KB with register ILP, vs single-thread-issue
//    bulk copy). Attacks the in-flight-bytes deficit behind the 3.2TB/s wall.
//  - D[27] computed redundantly per block, overlapped with the copies.
// ---------------------------------------------------------------------------

static constexpr int TPB  = 256;
static constexpr int ROWS = 2048;              // rows per block
static constexpr int PER_THREAD = ROWS / TPB;  // 8 cp.asyncs / thread

__device__ __forceinline__ void swp(float& a, float& b) { float t = a; a = b; b = t; }

__device__ __forceinline__ float vqc_eval(const float* __restrict__ D,
                                          float x0, float x1, float x2) {
    float s0, c0, s1, c1, s2, c2;
    __sincosf(x0, &s0, &c0);
    __sincosf(x1, &s1, &c1);
    __sincosf(x2, &s2, &c2);

    float z = 0.f;
    #pragma unroll
    for (int p0 = 0; p0 < 3; p0++) {
        float u = 0.f;
        #pragma unroll
        for (int p1 = 0; p1 < 3; p1++) {
            const float* d = &D[p0 * 9 + p1 * 3];
            float v = fmaf(d[2], s2, fmaf(d[1], c2, d[0]));
            float m1 = (p1 == 0) ? 1.f : ((p1 == 1) ? c1 : s1);
            u = fmaf(v, m1, u);
        }
        float m0 = (p0 == 0) ? 1.f : ((p0 == 1) ? c0 : s0);
        z = fmaf(u, m0, z);
    }
    return z;
}

__global__ void __launch_bounds__(TPB, 6) vqc_kernel(
    const float* __restrict__ in,  // (B, 8) floats, rows 32B
    const float* __restrict__ w,   // (3,3,2) = 18 floats
    float* __restrict__ out,       // (B,)
    int B
) {
    __shared__ __align__(128) float4 xs[ROWS];        // 32 KB: 16B per row
    __shared__ float Ur[8][8], Ui[8][8], Ms[8][8], Dsh[27];

    const int t = threadIdx.x;
    const int base = blockIdx.x * ROWS;
    const int rows = min(ROWS, B - base);

    // ---- issue all copies first: 256 threads x 8 x 16B = 32KB in flight ----
    #pragma unroll
    for (int k = 0; k < PER_THREAD; k++) {
        int r = t + k * TPB;
        if (r < rows) {
            unsigned dst = (unsigned)__cvta_generic_to_shared(&xs[r]);
            const float* src = in + (size_t)(base + r) * 8;  // first 16B of row
            asm volatile("cp.async.cg.shared.global [%0], [%1], 16;"
                         :: "r"(dst), "l"(src) : "memory");
        }
    }
    asm volatile("cp.async.commit_group;" ::: "memory");

    // ---- fused setup, overlapped with the in-flight copies ----
    if (t < 8) {
        // Evolve basis column j = t through the parameterized circuit.
        float ur[8], ui[8];
        #pragma unroll
        for (int k = 0; k < 8; k++) { ur[k] = (k == t) ? 1.f : 0.f; ui[k] = 0.f; }

        for (int l = 0; l < 3; l++) {
            for (int q = 0; q < 3; q++) {
                float thy = w[(l * 3 + q) * 2 + 0];
                float thz = w[(l * 3 + q) * 2 + 1];
                int s = 4 >> q;  // bit stride: q0->4, q1->2, q2->1

                // RY: real rotation on (i, i+s) pairs. __sincosf abs err ~1e-7.
                float cy, sy; __sincosf(0.5f * thy, &sy, &cy);
                #pragma unroll
                for (int i = 0; i < 8; i++) {
                    if (i & s) continue;
                    float ar = ur[i],     ai = ui[i];
                    float br = ur[i + s], bi = ui[i + s];
                    ur[i]     = cy * ar - sy * br;  ui[i]     = cy * ai - sy * bi;
                    ur[i + s] = sy * ar + cy * br;  ui[i + s] = sy * ai + cy * bi;
                }
                // RZ: bit=0 -> e^{-i thz/2}, bit=1 -> e^{+i thz/2}
                float cz, sz; __sincosf(0.5f * thz, &sz, &cz);
                #pragma unroll
                for (int i = 0; i < 8; i++) {
                    float ph = (i & s) ? sz : -sz;
                    float ar = ur[i], ai = ui[i];
                    ur[i] = cz * ar - ph * ai;
                    ui[i] = cz * ai + ph * ar;
                }
            }
            // CNOT01: swap 4<->6, 5<->7 ; CNOT12: swap 2<->3, 6<->7
            swp(ur[4], ur[6]); swp(ui[4], ui[6]);
            swp(ur[5], ur[7]); swp(ui[5], ui[7]);
            swp(ur[2], ur[3]); swp(ui[2], ui[3]);
            swp(ur[6], ur[7]); swp(ui[6], ui[7]);
        }
        #pragma unroll
        for (int k = 0; k < 8; k++) { Ur[k][t] = ur[k]; Ui[k][t] = ui[k]; }
    }
    __syncthreads();

    if (t < 64) {
        // ReM[i][j] = sum_k sign(k) Re(conj(U[k][i]) U[k][j]); sign=+1 for k<4.
        int i = t >> 3, j = t & 7;
        float m = 0.f;
        #pragma unroll
        for (int k = 0; k < 8; k++) {
            float sgn = (k < 4) ? 1.f : -1.f;
            m += sgn * (Ur[k][i] * Ur[k][j] + Ui[k][i] * Ui[k][j]);
        }
        Ms[i][j] = m;
    }
    __syncthreads();

    if (t < 27) {
        // Pair-(b,b') -> (1, cos, sin): c^2 = .5+.5cos, cs = .5sin, s^2 = .5-.5cos
        const float T[4][3] = {
            {0.5f,  0.5f, 0.0f}, {0.0f, 0.0f, 0.5f},
            {0.0f,  0.0f, 0.5f}, {0.5f, -0.5f, 0.0f},
        };
        int p0 = t / 9, p1 = (t / 3) % 3, p2 = t % 3;
        float d = 0.f;
        #pragma unroll
        for (int i = 0; i < 8; i++) {
            #pragma unroll
            for (int j = 0; j < 8; j++) {
                int pr0 = (((i >> 2) & 1) << 1) | ((j >> 2) & 1);
                int pr1 = (((i >> 1) & 1) << 1) | ((j >> 1) & 1);
                int pr2 = ((i & 1) << 1) | (j & 1);
                d += Ms[i][j] * T[pr0][p0] * T[pr1][p1] * T[pr2][p2];
            }
        }
        Dsh[t] = d;
    }
    __syncthreads();

    float D[27];
    #pragma unroll
    for (int i = 0; i < 27; i++) D[i] = Dsh[i];

    // ---- drain copies, then compute from SMEM ----
    asm volatile("cp.async.wait_group 0;" ::: "memory");
    __syncthreads();

    #pragma unroll
    for (int k = 0; k < PER_THREAD; k++) {
        int r = t + k * TPB;
        if (r < rows) {
            float4 x = xs[r];
            out[base + r] = vqc_eval(D, x.x, x.y, x.z);
        }
    }
}

extern "C" void kernel_launch(void* const* d_in, const int* in_sizes, int n_in,
                              void* d_out, int out_size) {
    // inputs: (B,8) float32; q_weights: (3,3,2)=18 float32.  Be robust to order.
    const float* in = (const float*)d_in[0];
    const float* w  = (const float*)d_in[1];
    int sz0 = in_sizes[0], sz1 = in_sizes[1];
    if (sz0 == 18 && sz1 != 18) {
        const float* tmp = in; in = w; w = tmp;
        int ts = sz0; sz0 = sz1; sz1 = ts;
    }
    int B = sz0 / 8;
    float* out = (float*)d_out;

    int grid = (B + ROWS - 1) / ROWS;
    vqc_kernel<<<grid, TPB>>>(in, w, out, B);
}

// round 15
// speedup vs baseline: 1.0201x; 1.0201x over previous
#include <cuda_runtime.h>
#include <cuda_bf16.h>

// ---------------------------------------------------------------------------
// QuantumLayerVQC — 3-qubit, 3-layer VQC, B ~ 1M samples.
//
// z(b) = psi(b)^T ReM psi(b), psi = kron_q (cos x_q/2, sin x_q/2),
// ReM = Re(U^dag Z0 U) depends only on q_weights. Per qubit the quadratic
// monomials {c^2, s^2, cs} map to {1, cos x, sin x} (double angle), so z is
// trilinear in m_q = (1, cos x_q, sin x_q) with 27 coefficients D.
//
// EXPERIMENT this round: rows are 32B = one full sector, but we previously
// requested only the first 16B of each -> every transaction half-useful.
// Now each thread requests the FULL 32B row (two LDG.128, hi half kept live
// via a runtime-zero FMA) to test the partial-sector-bandwidth theory.
// ---------------------------------------------------------------------------

__device__ float g_D[27];
__device__ float g_zero;   // written 0.0f by setup kernel; defeats DCE of hi loads

__device__ __forceinline__ void swp(float& a, float& b) { float t = a; a = b; b = t; }

__global__ void vqc_setup_kernel(const float* __restrict__ w) {
    // w: (3 layers, 3 qubits, 2) = 18 floats: [l][q][0]=RY angle, [l][q][1]=RZ angle
    __shared__ float Ur[8][8];  // [amplitude k][column j]
    __shared__ float Ui[8][8];
    __shared__ float Ms[8][8];  // ReM

    int t = threadIdx.x;
    if (t == 0) g_zero = 0.0f;

    if (t < 8) {
        // Evolve basis column j = t through the parameterized circuit.
        float ur[8], ui[8];
        #pragma unroll
        for (int k = 0; k < 8; k++) { ur[k] = (k == t) ? 1.f : 0.f; ui[k] = 0.f; }

        for (int l = 0; l < 3; l++) {
            for (int q = 0; q < 3; q++) {
                float thy = w[(l * 3 + q) * 2 + 0];
                float thz = w[(l * 3 + q) * 2 + 1];
                int s = 4 >> q;  // bit stride: q0->4, q1->2, q2->1

                // RY: real rotation on (i, i+s) pairs. __sincosf abs err ~1e-7,
                // far under the 1e-3 rel-err budget.
                float cy, sy; __sincosf(0.5f * thy, &sy, &cy);
                #pragma unroll
                for (int i = 0; i < 8; i++) {
                    if (i & s) continue;
                    float ar = ur[i],     ai = ui[i];
                    float br = ur[i + s], bi = ui[i + s];
                    ur[i]     = cy * ar - sy * br;  ui[i]     = cy * ai - sy * bi;
                    ur[i + s] = sy * ar + cy * br;  ui[i + s] = sy * ai + cy * bi;
                }
                // RZ: bit=0 -> e^{-i thz/2}, bit=1 -> e^{+i thz/2}
                float cz, sz; __sincosf(0.5f * thz, &sz, &cz);
                #pragma unroll
                for (int i = 0; i < 8; i++) {
                    float ph = (i & s) ? sz : -sz;  // imaginary part of phase
                    float ar = ur[i], ai = ui[i];
                    ur[i] = cz * ar - ph * ai;
                    ui[i] = cz * ai + ph * ar;
                }
            }
            // CNOT01: swap 4<->6, 5<->7 ; CNOT12: swap 2<->3, 6<->7
            swp(ur[4], ur[6]); swp(ui[4], ui[6]);
            swp(ur[5], ur[7]); swp(ui[5], ui[7]);
            swp(ur[2], ur[3]); swp(ui[2], ui[3]);
            swp(ur[6], ur[7]); swp(ui[6], ui[7]);
        }
        #pragma unroll
        for (int k = 0; k < 8; k++) { Ur[k][t] = ur[k]; Ui[k][t] = ui[k]; }
    }
    __syncthreads();

    if (t < 64) {
        // ReM[i][j] = sum_k sign(k) Re(conj(U[k][i]) U[k][j]); sign=+1 for k<4.
        int i = t >> 3, j = t & 7;
        float m = 0.f;
        #pragma unroll
        for (int k = 0; k < 8; k++) {
            float sgn = (k < 4) ? 1.f : -1.f;
            m += sgn * (Ur[k][i] * Ur[k][j] + Ui[k][i] * Ui[k][j]);
        }
        Ms[i][j] = m;
    }
    __syncthreads();

    if (t < 27) {
        // Pair-(b,b') -> (1, cos, sin): c^2 = .5+.5cos, cs = .5sin, s^2 = .5-.5cos
        const float T[4][3] = {
            {0.5f,  0.5f, 0.0f}, {0.0f, 0.0f, 0.5f},
            {0.0f,  0.0f, 0.5f}, {0.5f, -0.5f, 0.0f},
        };
        int p0 = t / 9, p1 = (t / 3) % 3, p2 = t % 3;
        float d = 0.f;
        #pragma unroll
        for (int i = 0; i < 8; i++) {
            #pragma unroll
            for (int j = 0; j < 8; j++) {
                int pr0 = (((i >> 2) & 1) << 1) | ((j >> 2) & 1);
                int pr1 = (((i >> 1) & 1) << 1) | ((j >> 1) & 1);
                int pr2 = ((i & 1) << 1) | (j & 1);
                d += Ms[i][j] * T[pr0][p0] * T[pr1][p1] * T[pr2][p2];
            }
        }
        g_D[t] = d;
    }
}

static constexpr int TPB = 256;
static constexpr int ILP = 4;   // rows per thread; 2 LDG.128 per row (full sector)

__device__ __forceinline__ float vqc_eval(const float* __restrict__ D,
                                          float x0, float x1, float x2) {
    float s0, c0, s1, c1, s2, c2;
    __sincosf(x0, &s0, &c0);
    __sincosf(x1, &s1, &c1);
    __sincosf(x2, &s2, &c2);

    float z = 0.f;
    #pragma unroll
    for (int p0 = 0; p0 < 3; p0++) {
        float u = 0.f;
        #pragma unroll
        for (int p1 = 0; p1 < 3; p1++) {
            const float* d = &D[p0 * 9 + p1 * 3];
            float v = fmaf(d[2], s2, fmaf(d[1], c2, d[0]));
            float m1 = (p1 == 0) ? 1.f : ((p1 == 1) ? c1 : s1);
            u = fmaf(v, m1, u);
        }
        float m0 = (p0 == 0) ? 1.f : ((p0 == 1) ? c0 : s0);
        z = fmaf(u, m0, z);
    }
    return z;
}

__global__ void __launch_bounds__(TPB) vqc_main_kernel(
    const float4* __restrict__ in,  // (B, 8) floats = (B, 2) float4
    float* __restrict__ out,        // (B,)
    int B
) {
    int base = blockIdx.x * (TPB * ILP) + threadIdx.x;
    float zk = g_zero;  // runtime 0.0f — keeps hi-half loads alive

    if (base + (ILP - 1) * TPB < B) {
        // Fast path: request the FULL 32B sector of each row (lo+hi LDG.128),
        // all loads front-batched.
        float4 lo[ILP], hi[ILP];
        #pragma unroll
        for (int it = 0; it < ILP; it++) {
            int idx = base + it * TPB;
            lo[it] = __ldg(in + idx * 2);
            hi[it] = __ldg(in + idx * 2 + 1);
        }

        float D[27];
        #pragma unroll
        for (int i = 0; i < 27; i++) D[i] = g_D[i];

        #pragma unroll
        for (int it = 0; it < ILP; it++) {
            float z = vqc_eval(D, lo[it].x, lo[it].y, lo[it].z);
            // zk == 0.0 at runtime: forces the hi load, adds nothing.
            z = fmaf(zk, hi[it].x + hi[it].w, z);
            out[base + it * TPB] = z;
        }
    } else {
        float D[27];
        #pragma unroll
        for (int i = 0; i < 27; i++) D[i] = g_D[i];
        #pragma unroll
        for (int it = 0; it < ILP; it++) {
            int idx = base + it * TPB;
            if (idx < B) {
                float4 lo = __ldg(in + idx * 2);
                float4 hi = __ldg(in + idx * 2 + 1);
                float z = vqc_eval(D, lo.x, lo.y, lo.z);
                z = fmaf(zk, hi.x + hi.w, z);
                out[idx] = z;
            }
        }
    }
}

extern "C" void kernel_launch(void* const* d_in, const int* in_sizes, int n_in,
                              void* d_out, int out_size) {
    // inputs: (B,8) float32; q_weights: (3,3,2)=18 float32.  Be robust to order.
    const float* in = (const float*)d_in[0];
    const float* w  = (const float*)d_in[1];
    int sz0 = in_sizes[0], sz1 = in_sizes[1];
    if (sz0 == 18 && sz1 != 18) {
        const float* tmp = in; in = w; w = tmp;
        int ts = sz0; sz0 = sz1; sz1 = ts;
    }
    int B = sz0 / 8;
    float* out = (float*)d_out;

    vqc_setup_kernel<<<1, 64>>>(w);
    int grid = (B + TPB * ILP - 1) / (TPB * ILP);
    vqc_main_kernel<<<grid, TPB>>>(reinterpret_cast<const float4*>(in), out, B);
}